// round 15
// baseline (speedup 1.0000x reference)
#include <cuda_runtime.h>
#include <cuda_bf16.h>

#define THREADS 512
#define NBLK 1024

// ---- smem byte offsets ----
#define XHI 0u            // X hi  [128][128] bf16, rowbytes 256, swizzled   (32KB); later W-bf16 hi [256][32]
#define XLO 32768u        // X lo                                            (32KB); later W-bf16 lo
#define STGH 65536u       // stage hi [128][256] bf16, rowbytes 512, swz     (64KB)  T then V
#define STGL 131072u      // stage lo                                        (64KB)
#define SCOR 196608u      // scores/weights fp32 [256][34]                   (34816B)
#define SMEM_BYTES 231424u
#define SC_STRIDE 34

// packed W fragments: [octet o (0..63)][kt (0..7)][lane (0..31)] -> uint4 {bh0,bh1,bl0,bl1}
__device__ __align__(16) unsigned short g_wpk[64 * 8 * 32 * 8];

// ================= prep kernel =================
__global__ void prep_w(const float* __restrict__ WQ, const float* __restrict__ WK,
                       const float* __restrict__ WV)
{
    const int n = blockIdx.x, k1 = threadIdx.x;
    __shared__ float wk[128];
    float val;
    if (n < 256) {
        val = WV[k1 * 256 + n];
    } else {
        const int h = (n - 256) >> 7, k2 = (n - 256) & 127;
        wk[k1] = WK[k2 * 256 + h * 128 + k1];
        __syncthreads();
        const float* wq = WQ + k1 * 256 + h * 128;
        float acc = 0.f;
#pragma unroll 8
        for (int e = 0; e < 128; ++e) acc = fmaf(wq[e], wk[e], acc);
        val = acc * 0.0625f;       // fold 1/sqrt(D*H)
    }
    __nv_bfloat16 hi = __float2bfloat16(val);
    __nv_bfloat16 lo = __float2bfloat16(val - __bfloat162float(hi));

    const int o = n >> 3, grp = n & 7;
    const int kt = k1 >> 4, rem = k1 & 15;
    const int half = rem >> 3, q = (rem & 7) >> 1, parity = rem & 1;
    const int lane = grp * 4 + q;
    const size_t base = ((size_t)((o * 8 + kt) * 32) + lane) * 8;
    g_wpk[base + half * 2 + parity]     = __bfloat16_as_ushort(hi);
    g_wpk[base + 4 + half * 2 + parity] = __bfloat16_as_ushort(lo);
}

// ================= helpers =================
__device__ __forceinline__ unsigned swz(int r, unsigned off) {
    return off ^ (((unsigned)r & 7u) << 4);
}
__device__ __forceinline__ void stsm(unsigned char* smp, unsigned base, int r, int c, int rb, unsigned v) {
    *(unsigned*)(smp + base + swz(r, (unsigned)(r * rb + c * 2))) = v;
}
__device__ __forceinline__ void split2(float a, float b, unsigned& hi, unsigned& lo) {
    __nv_bfloat16 ha = __float2bfloat16(a), hb = __float2bfloat16(b);
    float la = a - __bfloat162float(ha), lb = b - __bfloat162float(hb);
    __nv_bfloat16 lA = __float2bfloat16(la), lB = __float2bfloat16(lb);
    hi = ((unsigned)__bfloat16_as_ushort(hb) << 16) | (unsigned)__bfloat16_as_ushort(ha);
    lo = ((unsigned)__bfloat16_as_ushort(lB) << 16) | (unsigned)__bfloat16_as_ushort(lA);
}
__device__ __forceinline__ void mma_bf(float* d, const unsigned* a, const unsigned* b) {
    asm volatile(
        "mma.sync.aligned.m16n8k16.row.col.f32.bf16.bf16.f32 "
        "{%0,%1,%2,%3}, {%4,%5,%6,%7}, {%8,%9}, {%0,%1,%2,%3};\n"
        : "+f"(d[0]), "+f"(d[1]), "+f"(d[2]), "+f"(d[3])
        : "r"(a[0]), "r"(a[1]), "r"(a[2]), "r"(a[3]), "r"(b[0]), "r"(b[1]));
}
__device__ __forceinline__ void ldmx4(unsigned a, unsigned& r0, unsigned& r1,
                                      unsigned& r2, unsigned& r3) {
    asm volatile("ldmatrix.sync.aligned.m8n8.x4.shared.b16 {%0,%1,%2,%3}, [%4];"
                 : "=r"(r0), "=r"(r1), "=r"(r2), "=r"(r3) : "r"(a));
}
__device__ __forceinline__ void ldmx4t(unsigned a, unsigned& r0, unsigned& r1,
                                       unsigned& r2, unsigned& r3) {
    asm volatile("ldmatrix.sync.aligned.m8n8.x4.trans.shared.b16 {%0,%1,%2,%3}, [%4];"
                 : "=r"(r0), "=r"(r1), "=r"(r2), "=r"(r3) : "r"(a));
}

// projection GEMM: warp computes rows [mh*64, mh*64+64) x cols [nb, nb+8*P) of
// Y = X(128x128) * Wbig(128x512) slice; 3-pass compensated bf16; stage to STG.
template<int P>
__device__ __forceinline__ void proj_gemm(unsigned char* smp, unsigned sb,
                                          int nsel, int nb, int mh,
                                          int lane, int grp, int q)
{
    const int mi = lane >> 3, lr = lane & 7;
    const unsigned xsw = (unsigned)lr << 4;
    unsigned offA[4];
#pragma unroll
    for (int m = 0; m < 4; ++m)
        offA[m] = (unsigned)((mh * 64 + m * 16 + (mi & 1) * 8 + lr) * 256 + (mi >> 1) * 16);

    float D[P][4][4];
#pragma unroll
    for (int p = 0; p < P; ++p)
#pragma unroll
        for (int m = 0; m < 4; ++m)
#pragma unroll
            for (int e = 0; e < 4; ++e) D[p][m][e] = 0.f;

    const uint4* wp = (const uint4*)g_wpk;
    const int ob = (nsel + nb) >> 3;
    unsigned wbase[P];
#pragma unroll
    for (int p = 0; p < P; ++p)
        wbase[p] = (unsigned)((ob + p) * 256 + lane);

#pragma unroll
    for (int kt = 0; kt < 8; ++kt) {
        unsigned bh[P][2], bl[P][2];
#pragma unroll
        for (int p = 0; p < P; ++p) {
            const uint4 v = wp[wbase[p] + kt * 32];
            bh[p][0] = v.x; bh[p][1] = v.y;
            bl[p][0] = v.z; bl[p][1] = v.w;
        }
        const unsigned ck = (unsigned)(kt * 32);
        unsigned A[4][4];
#pragma unroll
        for (int m = 0; m < 4; ++m)
            ldmx4(sb + XHI + ((offA[m] + ck) ^ xsw), A[m][0], A[m][1], A[m][2], A[m][3]);
#pragma unroll
        for (int p = 0; p < P; ++p)
#pragma unroll
            for (int m = 0; m < 4; ++m) mma_bf(D[p][m], A[m], bh[p]);
#pragma unroll
        for (int p = 0; p < P; ++p)
#pragma unroll
            for (int m = 0; m < 4; ++m) mma_bf(D[p][m], A[m], bl[p]);
        // reload A with XLO in the same registers
#pragma unroll
        for (int m = 0; m < 4; ++m)
            ldmx4(sb + XLO + ((offA[m] + ck) ^ xsw), A[m][0], A[m][1], A[m][2], A[m][3]);
#pragma unroll
        for (int p = 0; p < P; ++p)
#pragma unroll
            for (int m = 0; m < 4; ++m) mma_bf(D[p][m], A[m], bh[p]);
    }

    // stage (split hi/lo)
#pragma unroll
    for (int p = 0; p < P; ++p)
#pragma unroll
        for (int m = 0; m < 4; ++m) {
            const int r0 = mh * 64 + m * 16 + grp;
            const int c = nb + p * 8 + 2 * q;
            unsigned hi, lo;
            split2(D[p][m][0], D[p][m][1], hi, lo);
            stsm(smp, STGH, r0, c, 512, hi);
            stsm(smp, STGL, r0, c, 512, lo);
            split2(D[p][m][2], D[p][m][3], hi, lo);
            stsm(smp, STGH, r0 + 8, c, 512, hi);
            stsm(smp, STGL, r0 + 8, c, 512, lo);
        }
}

// ================= main kernel: 1 CTA = 4 graphs, 16 warps =================
__global__ __launch_bounds__(THREADS, 1)
void attn_hmma(const float* __restrict__ x,
               float* __restrict__ out,      // [B*N, 128]
               float* __restrict__ weight)   // [B*N, 32, 2]
{
    extern __shared__ unsigned char smp[];
    const unsigned sb = (unsigned)__cvta_generic_to_shared(smp);
    const int t = threadIdx.x;
    const int w = t >> 5, lane = t & 31, grp = lane >> 2, q = lane & 3;
    const int mi = lane >> 3, lr = lane & 7;
    const unsigned xsw = (unsigned)lr << 4;

    // ---- load X, split hi/lo ----
    {
        const float2* xg = (const float2*)(x + (size_t)blockIdx.x * 16384);
#pragma unroll
        for (int it = 0; it < 16; ++it) {
            const int e2 = t + 512 * it;
            const float2 v = xg[e2];
            const int r = e2 >> 6, c = (e2 & 63) * 2;
            unsigned hi, lo;
            split2(v.x, v.y, hi, lo);
            stsm(smp, XHI, r, c, 256, hi);
            stsm(smp, XLO, r, c, 256, lo);
        }
    }
    __syncthreads();

    // ---- phase T: T = X * A_h^T (octets 32..63), staged [128][256] (h,k2) ----
    proj_gemm<4>(smp, sb, 256, (w >> 1) * 32, w & 1, lane, grp, q);
    __syncthreads();

    // ---- phase S: warp (g, h, ih): 16 i-rows of S_gh[32x32] = T_gh * X_g^T ----
    {
        const int g = w >> 2, h = (w >> 1) & 1, ih = w & 1;
        float D[4][4];
#pragma unroll
        for (int nt = 0; nt < 4; ++nt)
#pragma unroll
            for (int e = 0; e < 4; ++e) D[nt][e] = 0.f;

        const unsigned offSA = (unsigned)((g * 32 + ih * 16 + (mi & 1) * 8 + lr) * 512
                                          + (mi >> 1) * 16 + h * 256);
        const unsigned offSB = (unsigned)((g * 32 + (mi >> 1) * 8 + lr) * 256 + (mi & 1) * 16);

#pragma unroll
        for (int kt = 0; kt < 8; ++kt) {
            const unsigned ck = (unsigned)(kt * 32);
            unsigned Ah[4], Al[4];
            ldmx4(sb + STGH + ((offSA + ck) ^ xsw), Ah[0], Ah[1], Ah[2], Ah[3]);
            ldmx4(sb + STGL + ((offSA + ck) ^ xsw), Al[0], Al[1], Al[2], Al[3]);
            unsigned Bh[4][2], Bl[4][2];
            ldmx4(sb + XHI + ((offSB + ck) ^ xsw),        Bh[0][0], Bh[0][1], Bh[1][0], Bh[1][1]);
            ldmx4(sb + XHI + ((offSB + 4096 + ck) ^ xsw), Bh[2][0], Bh[2][1], Bh[3][0], Bh[3][1]);
            ldmx4(sb + XLO + ((offSB + ck) ^ xsw),        Bl[0][0], Bl[0][1], Bl[1][0], Bl[1][1]);
            ldmx4(sb + XLO + ((offSB + 4096 + ck) ^ xsw), Bl[2][0], Bl[2][1], Bl[3][0], Bl[3][1]);
            // pass-outer: per-accumulator order (AhBh, AlBh, AhBl) preserved
#pragma unroll
            for (int nt = 0; nt < 4; ++nt) mma_bf(D[nt], Ah, Bh[nt]);
#pragma unroll
            for (int nt = 0; nt < 4; ++nt) mma_bf(D[nt], Al, Bh[nt]);
#pragma unroll
            for (int nt = 0; nt < 4; ++nt) mma_bf(D[nt], Ah, Bl[nt]);
        }
        // stage scores fp32
        float* sc = (float*)(smp + SCOR);
#pragma unroll
        for (int nt = 0; nt < 4; ++nt) {
            const int p = g * 64 + h * 32 + ih * 16 + grp;
            const int j = nt * 8 + 2 * q;
            float2 v0; v0.x = D[nt][0]; v0.y = D[nt][1];
            float2 v1; v1.x = D[nt][2]; v1.y = D[nt][3];
            *(float2*)&sc[p * SC_STRIDE + j] = v0;
            *(float2*)&sc[(p + 8) * SC_STRIDE + j] = v1;
        }
    }
    __syncthreads();

    // ---- split: warps 0-7 sparsemax+weight write; warps 8-15 start phase V (cols 0..127) ----
    if (w < 8) {
        // sparsemax: thread t (0..255) owns problem p = t; in-place
        float* zrow = (float*)(smp + SCOR) + t * SC_STRIDE;
        float z[32], s[32];
#pragma unroll
        for (int j = 0; j < 32; ++j) { z[j] = zrow[j]; s[j] = z[j]; }
        // bitonic sort, descending, fully unrolled (240 compare-exchanges)
#pragma unroll
        for (int k = 2; k <= 32; k <<= 1) {
#pragma unroll
            for (int j = k >> 1; j > 0; j >>= 1) {
#pragma unroll
                for (int i = 0; i < 32; ++i) {
                    const int l = i ^ j;
                    if (l > i) {
                        const float a = s[i], b = s[l];
                        const float hi = fmaxf(a, b), lo = fminf(a, b);
                        if ((i & k) == 0) { s[i] = hi; s[l] = lo; }
                        else              { s[i] = lo; s[l] = hi; }
                    }
                }
            }
        }
        float csum = 0.f, ssum = 0.f; int ksup = 0;
#pragma unroll
        for (int kk = 1; kk <= 32; ++kk) {
            const float zk = s[kk - 1];
            csum += zk;
            if (1.0f + (float)kk * zk > csum) { ksup += 1; ssum += zk; }
        }
        const float tau = (ssum - 1.0f) / (float)ksup;
#pragma unroll
        for (int j = 0; j < 32; ++j) zrow[j] = fmaxf(z[j] - tau, 0.f);

        asm volatile("bar.sync 1, 256;" ::: "memory");

        // weight -> gmem (256 threads, 16 iters)
        float2* wg = (float2*)(weight + (size_t)blockIdx.x * 8192);
        const float* sc = (const float*)(smp + SCOR);
#pragma unroll
        for (int it = 0; it < 16; ++it) {
            const int idx = t + 256 * it;       // (gi, j)
            const int gi = idx >> 5, j = idx & 31;
            const int g = gi >> 5, i = gi & 31;
            float2 o;
            o.x = sc[(g * 64 + i) * SC_STRIDE + j];
            o.y = sc[(g * 64 + 32 + i) * SC_STRIDE + j];
            wg[idx] = o;
        }
    } else {
        // phase V first half: V = X * WV, cols 0..127 (8 warps)
        const int idx = w - 8;
        proj_gemm<4>(smp, sb, 0, (idx & 3) * 32, idx >> 2, lane, grp, q);
    }
    __syncthreads();

    // ---- phase V second half: cols 128..255 (16 warps, 16 cols each) ----
    proj_gemm<2>(smp, sb, 0, 128 + (w >> 1) * 16, w & 1, lane, grp, q);
    __syncthreads();

    // ---- convert sparsemax weights (0.5-folded) to bf16 hi/lo into X region ----
    // layout: [256 rows p][32 cols j], rowbytes 64, chunk-XOR swizzle (conflict-free ldmatrix)
    {
        const float* sc = (const float*)(smp + SCOR);
        const int p = t >> 1, jh = (t & 1) * 16;
        const unsigned rsw = (((unsigned)p >> 1) & 3u) << 4;
        const unsigned rbase = (unsigned)(p * 64);
#pragma unroll
        for (int jj = 0; jj < 16; jj += 2) {
            const int j = jh + jj;
            const float2 f = *(const float2*)&sc[p * SC_STRIDE + j];
            unsigned hi, lo;
            split2(0.5f * f.x, 0.5f * f.y, hi, lo);
            const unsigned off = rbase + ((((unsigned)j >> 3) << 4) ^ rsw) + (unsigned)((j & 7) * 2);
            *(unsigned*)(smp + XHI + off) = hi;
            *(unsigned*)(smp + XLO + off) = lo;
        }
    }
    __syncthreads();

    // ---- phase O: warp (g, dq): O_g[32 x 32] = (0.5*w) * V, both heads in K ----
    {
        const int g = w >> 2, dq = w & 3;
        float D[4][2][4];
#pragma unroll
        for (int n = 0; n < 4; ++n)
#pragma unroll
            for (int m = 0; m < 2; ++m)
#pragma unroll
                for (int e = 0; e < 4; ++e) D[n][m][e] = 0.f;

        const unsigned offOB = (unsigned)((g * 32 + (mi & 1) * 8 + lr) * 512
                                          + (mi >> 1) * 16 + dq * 64);

#pragma unroll
        for (int kt = 0; kt < 4; ++kt) {
            const int h = kt >> 1, jb = (kt & 1) * 16;
            unsigned Ah[2][4], Al[2][4];
#pragma unroll
            for (int m = 0; m < 2; ++m) {
                const int prow = g * 64 + h * 32 + m * 16 + (mi & 1) * 8 + lr;
                const int cch = (jb >> 3) + (mi >> 1);
                const unsigned aoff = (unsigned)(prow * 64)
                    + (((unsigned)(cch ^ ((prow >> 1) & 3))) << 4);
                ldmx4(sb + XHI + aoff, Ah[m][0], Ah[m][1], Ah[m][2], Ah[m][3]);
                ldmx4(sb + XLO + aoff, Al[m][0], Al[m][1], Al[m][2], Al[m][3]);
            }
            const unsigned koff = (unsigned)((kt & 1) * 8192 + (kt >> 1) * 256);
            unsigned Bh[4][2], Bl[4][2];
            ldmx4t(sb + STGH + ((offOB + koff) ^ xsw),      Bh[0][0], Bh[0][1], Bh[1][0], Bh[1][1]);
            ldmx4t(sb + STGH + ((offOB + koff + 32) ^ xsw), Bh[2][0], Bh[2][1], Bh[3][0], Bh[3][1]);
            ldmx4t(sb + STGL + ((offOB + koff) ^ xsw),      Bl[0][0], Bl[0][1], Bl[1][0], Bl[1][1]);
            ldmx4t(sb + STGL + ((offOB + koff + 32) ^ xsw), Bl[2][0], Bl[2][1], Bl[3][0], Bl[3][1]);
            // pass-outer: per-accumulator order (AhBh, AlBh, AhBl) preserved
#pragma unroll
            for (int n = 0; n < 4; ++n)
#pragma unroll
                for (int m = 0; m < 2; ++m) mma_bf(D[n][m], Ah[m], Bh[n]);
#pragma unroll
            for (int n = 0; n < 4; ++n)
#pragma unroll
                for (int m = 0; m < 2; ++m) mma_bf(D[n][m], Al[m], Bh[n]);
#pragma unroll
            for (int n = 0; n < 4; ++n)
#pragma unroll
                for (int m = 0; m < 2; ++m) mma_bf(D[n][m], Ah[m], Bl[n]);
        }
        // out write
#pragma unroll
        for (int n = 0; n < 4; ++n)
#pragma unroll
            for (int m = 0; m < 2; ++m) {
                const int i = m * 16 + grp;
                const int d = dq * 32 + n * 8 + 2 * q;
                const size_t row = ((size_t)blockIdx.x * 4 + g) * 32 + i;
                float2 v0; v0.x = D[n][m][0]; v0.y = D[n][m][1];
                float2 v1; v1.x = D[n][m][2]; v1.y = D[n][m][3];
                *(float2*)&out[row * 128 + d] = v0;
                *(float2*)&out[(row + 8) * 128 + d] = v1;
            }
    }
}

extern "C" void kernel_launch(void* const* d_in, const int* in_sizes, int n_in,
                              void* d_out, int out_size)
{
    (void)in_sizes; (void)n_in; (void)out_size;
    const float* x  = (const float*)d_in[0];
    const float* WK = (const float*)d_in[1];
    const float* WV = (const float*)d_in[2];
    const float* WQ = (const float*)d_in[3];

    float* out    = (float*)d_out;
    float* weight = out + (size_t)4096 * 32 * 128;

    prep_w<<<512, 128>>>(WQ, WK, WV);

    cudaFuncSetAttribute(attn_hmma, cudaFuncAttributeMaxDynamicSharedMemorySize, SMEM_BYTES);
    attn_hmma<<<NBLK, THREADS, SMEM_BYTES>>>(x, out, weight);
}

// round 16
// speedup vs baseline: 1.5152x; 1.5152x over previous
#include <cuda_runtime.h>
#include <cuda_bf16.h>

#define THREADS 512
#define NBLK 1024

// ---- smem byte offsets ----
#define XHI 0u            // X hi  [128][128] bf16, rowbytes 256, swizzled   (32KB); later W-bf16 hi [256][32]
#define XLO 32768u        // X lo                                            (32KB); later W-bf16 lo
#define STGH 65536u       // stage hi [128][256] bf16, rowbytes 512, swz     (64KB)  T then V
#define STGL 131072u      // stage lo                                        (64KB)
#define SCOR 196608u      // scores/weights fp32 [256][34]                   (34816B)
#define SMEM_BYTES 231424u
#define SC_STRIDE 34

// packed W fragments: [octet o (0..63)][kt (0..7)][lane (0..31)] -> uint4 {bh0,bh1,bl0,bl1}
__device__ __align__(16) unsigned short g_wpk[64 * 8 * 32 * 8];

// ================= prep kernel =================
__global__ void prep_w(const float* __restrict__ WQ, const float* __restrict__ WK,
                       const float* __restrict__ WV)
{
    const int n = blockIdx.x, k1 = threadIdx.x;
    __shared__ float wk[128];
    float val;
    if (n < 256) {
        val = WV[k1 * 256 + n];
    } else {
        const int h = (n - 256) >> 7, k2 = (n - 256) & 127;
        wk[k1] = WK[k2 * 256 + h * 128 + k1];
        __syncthreads();
        const float* wq = WQ + k1 * 256 + h * 128;
        float acc = 0.f;
#pragma unroll 8
        for (int e = 0; e < 128; ++e) acc = fmaf(wq[e], wk[e], acc);
        val = acc * 0.0625f;       // fold 1/sqrt(D*H)
    }
    __nv_bfloat16 hi = __float2bfloat16(val);
    __nv_bfloat16 lo = __float2bfloat16(val - __bfloat162float(hi));

    const int o = n >> 3, grp = n & 7;
    const int kt = k1 >> 4, rem = k1 & 15;
    const int half = rem >> 3, q = (rem & 7) >> 1, parity = rem & 1;
    const int lane = grp * 4 + q;
    const size_t base = ((size_t)((o * 8 + kt) * 32) + lane) * 8;
    g_wpk[base + half * 2 + parity]     = __bfloat16_as_ushort(hi);
    g_wpk[base + 4 + half * 2 + parity] = __bfloat16_as_ushort(lo);
}

// ================= helpers =================
__device__ __forceinline__ unsigned swz(int r, unsigned off) {
    return off ^ (((unsigned)r & 7u) << 4);
}
__device__ __forceinline__ void stsm(unsigned char* smp, unsigned base, int r, int c, int rb, unsigned v) {
    *(unsigned*)(smp + base + swz(r, (unsigned)(r * rb + c * 2))) = v;
}
__device__ __forceinline__ void split2(float a, float b, unsigned& hi, unsigned& lo) {
    __nv_bfloat16 ha = __float2bfloat16(a), hb = __float2bfloat16(b);
    float la = a - __bfloat162float(ha), lb = b - __bfloat162float(hb);
    __nv_bfloat16 lA = __float2bfloat16(la), lB = __float2bfloat16(lb);
    hi = ((unsigned)__bfloat16_as_ushort(hb) << 16) | (unsigned)__bfloat16_as_ushort(ha);
    lo = ((unsigned)__bfloat16_as_ushort(lB) << 16) | (unsigned)__bfloat16_as_ushort(lA);
}
__device__ __forceinline__ void mma_bf(float* d, const unsigned* a, const unsigned* b) {
    asm volatile(
        "mma.sync.aligned.m16n8k16.row.col.f32.bf16.bf16.f32 "
        "{%0,%1,%2,%3}, {%4,%5,%6,%7}, {%8,%9}, {%0,%1,%2,%3};\n"
        : "+f"(d[0]), "+f"(d[1]), "+f"(d[2]), "+f"(d[3])
        : "r"(a[0]), "r"(a[1]), "r"(a[2]), "r"(a[3]), "r"(b[0]), "r"(b[1]));
}
__device__ __forceinline__ void ldmx4(unsigned a, unsigned& r0, unsigned& r1,
                                      unsigned& r2, unsigned& r3) {
    asm volatile("ldmatrix.sync.aligned.m8n8.x4.shared.b16 {%0,%1,%2,%3}, [%4];"
                 : "=r"(r0), "=r"(r1), "=r"(r2), "=r"(r3) : "r"(a));
}
__device__ __forceinline__ void ldmx4t(unsigned a, unsigned& r0, unsigned& r1,
                                       unsigned& r2, unsigned& r3) {
    asm volatile("ldmatrix.sync.aligned.m8n8.x4.trans.shared.b16 {%0,%1,%2,%3}, [%4];"
                 : "=r"(r0), "=r"(r1), "=r"(r2), "=r"(r3) : "r"(a));
}

// projection GEMM: warp computes rows [mh*64, mh*64+64) x cols [nb, nb+32) of
// Y = X(128x128) * Wbig(128x512) slice; 3-pass compensated bf16; stage to STG.
// A (X) fragments loaded once per kt, reused across all 4 n-octets.
__device__ __forceinline__ void proj_gemm(unsigned char* smp, unsigned sb,
                                          int nsel, int nb, int mh,
                                          int lane, int grp, int q)
{
    const int mi = lane >> 3, lr = lane & 7;
    const unsigned xsw = (unsigned)lr << 4;
    unsigned offA[4];
#pragma unroll
    for (int m = 0; m < 4; ++m)
        offA[m] = (unsigned)((mh * 64 + m * 16 + (mi & 1) * 8 + lr) * 256 + (mi >> 1) * 16);

    float D[4][4][4];   // [p = octet][m][4]
#pragma unroll
    for (int p = 0; p < 4; ++p)
#pragma unroll
        for (int m = 0; m < 4; ++m)
#pragma unroll
            for (int e = 0; e < 4; ++e) D[p][m][e] = 0.f;

    const uint4* wp = (const uint4*)g_wpk;
    const int ob = (nsel + nb) >> 3;
    unsigned wbase[4];
#pragma unroll
    for (int p = 0; p < 4; ++p)
        wbase[p] = (unsigned)((ob + p) * 256 + lane);

#pragma unroll
    for (int kt = 0; kt < 8; ++kt) {
        unsigned bh[4][2], bl[4][2];
#pragma unroll
        for (int p = 0; p < 4; ++p) {
            const uint4 v = wp[wbase[p] + kt * 32];
            bh[p][0] = v.x; bh[p][1] = v.y;
            bl[p][0] = v.z; bl[p][1] = v.w;
        }
        const unsigned ck = (unsigned)(kt * 32);
        unsigned A[4][4];
#pragma unroll
        for (int m = 0; m < 4; ++m)
            ldmx4(sb + XHI + ((offA[m] + ck) ^ xsw), A[m][0], A[m][1], A[m][2], A[m][3]);
#pragma unroll
        for (int p = 0; p < 4; ++p)
#pragma unroll
            for (int m = 0; m < 4; ++m) mma_bf(D[p][m], A[m], bh[p]);
#pragma unroll
        for (int p = 0; p < 4; ++p)
#pragma unroll
            for (int m = 0; m < 4; ++m) mma_bf(D[p][m], A[m], bl[p]);
        // reload A with XLO in the same registers
#pragma unroll
        for (int m = 0; m < 4; ++m)
            ldmx4(sb + XLO + ((offA[m] + ck) ^ xsw), A[m][0], A[m][1], A[m][2], A[m][3]);
#pragma unroll
        for (int p = 0; p < 4; ++p)
#pragma unroll
            for (int m = 0; m < 4; ++m) mma_bf(D[p][m], A[m], bh[p]);
    }

    // stage (split hi/lo)
#pragma unroll
    for (int p = 0; p < 4; ++p)
#pragma unroll
        for (int m = 0; m < 4; ++m) {
            const int r0 = mh * 64 + m * 16 + grp;
            const int c = nb + p * 8 + 2 * q;
            unsigned hi, lo;
            split2(D[p][m][0], D[p][m][1], hi, lo);
            stsm(smp, STGH, r0, c, 512, hi);
            stsm(smp, STGL, r0, c, 512, lo);
            split2(D[p][m][2], D[p][m][3], hi, lo);
            stsm(smp, STGH, r0 + 8, c, 512, hi);
            stsm(smp, STGL, r0 + 8, c, 512, lo);
        }
}

// ================= main kernel: 1 CTA = 4 graphs, 16 warps =================
__global__ __launch_bounds__(THREADS, 1)
void attn_hmma(const float* __restrict__ x,
               float* __restrict__ out,      // [B*N, 128]
               float* __restrict__ weight)   // [B*N, 32, 2]
{
    extern __shared__ unsigned char smp[];
    const unsigned sb = (unsigned)__cvta_generic_to_shared(smp);
    const int t = threadIdx.x;
    const int w = t >> 5, lane = t & 31, grp = lane >> 2, q = lane & 3;
    const int mi = lane >> 3, lr = lane & 7;
    const unsigned xsw = (unsigned)lr << 4;

    // ---- load X, split hi/lo ----
    {
        const float2* xg = (const float2*)(x + (size_t)blockIdx.x * 16384);
#pragma unroll
        for (int it = 0; it < 16; ++it) {
            const int e2 = t + 512 * it;
            const float2 v = xg[e2];
            const int r = e2 >> 6, c = (e2 & 63) * 2;
            unsigned hi, lo;
            split2(v.x, v.y, hi, lo);
            stsm(smp, XHI, r, c, 256, hi);
            stsm(smp, XLO, r, c, 256, lo);
        }
    }
    __syncthreads();

    // ---- phase T: T = X * A_h^T (octets 32..63), staged [128][256] (h,k2) ----
    proj_gemm(smp, sb, 256, (w >> 1) * 32, w & 1, lane, grp, q);
    __syncthreads();

    // ---- phase S: warp (g, h, ih): 16 i-rows of S_gh[32x32] = T_gh * X_g^T ----
    {
        const int g = w >> 2, h = (w >> 1) & 1, ih = w & 1;
        float D[4][4];
#pragma unroll
        for (int nt = 0; nt < 4; ++nt)
#pragma unroll
            for (int e = 0; e < 4; ++e) D[nt][e] = 0.f;

        const unsigned offSA = (unsigned)((g * 32 + ih * 16 + (mi & 1) * 8 + lr) * 512
                                          + (mi >> 1) * 16 + h * 256);
        const unsigned offSB = (unsigned)((g * 32 + (mi >> 1) * 8 + lr) * 256 + (mi & 1) * 16);

#pragma unroll
        for (int kt = 0; kt < 8; ++kt) {
            const unsigned ck = (unsigned)(kt * 32);
            unsigned Ah[4], Al[4];
            ldmx4(sb + STGH + ((offSA + ck) ^ xsw), Ah[0], Ah[1], Ah[2], Ah[3]);
            ldmx4(sb + STGL + ((offSA + ck) ^ xsw), Al[0], Al[1], Al[2], Al[3]);
            unsigned Bh[4][2], Bl[4][2];
            ldmx4(sb + XHI + ((offSB + ck) ^ xsw),        Bh[0][0], Bh[0][1], Bh[1][0], Bh[1][1]);
            ldmx4(sb + XHI + ((offSB + 4096 + ck) ^ xsw), Bh[2][0], Bh[2][1], Bh[3][0], Bh[3][1]);
            ldmx4(sb + XLO + ((offSB + ck) ^ xsw),        Bl[0][0], Bl[0][1], Bl[1][0], Bl[1][1]);
            ldmx4(sb + XLO + ((offSB + 4096 + ck) ^ xsw), Bl[2][0], Bl[2][1], Bl[3][0], Bl[3][1]);
            // pass-outer: per-accumulator order (AhBh, AlBh, AhBl) preserved
#pragma unroll
            for (int nt = 0; nt < 4; ++nt) mma_bf(D[nt], Ah, Bh[nt]);
#pragma unroll
            for (int nt = 0; nt < 4; ++nt) mma_bf(D[nt], Al, Bh[nt]);
#pragma unroll
            for (int nt = 0; nt < 4; ++nt) mma_bf(D[nt], Ah, Bl[nt]);
        }
        // stage scores fp32
        float* sc = (float*)(smp + SCOR);
#pragma unroll
        for (int nt = 0; nt < 4; ++nt) {
            const int p = g * 64 + h * 32 + ih * 16 + grp;
            const int j = nt * 8 + 2 * q;
            float2 v0; v0.x = D[nt][0]; v0.y = D[nt][1];
            float2 v1; v1.x = D[nt][2]; v1.y = D[nt][3];
            *(float2*)&sc[p * SC_STRIDE + j] = v0;
            *(float2*)&sc[(p + 8) * SC_STRIDE + j] = v1;
        }
    }
    __syncthreads();

    // ---- sparsemax: thread t<256 owns problem p = t (g,h,i); in-place ----
    if (t < 256) {
        float* zrow = (float*)(smp + SCOR) + t * SC_STRIDE;
        float z[32], s[32];
#pragma unroll
        for (int j = 0; j < 32; ++j) { z[j] = zrow[j]; s[j] = z[j]; }
        // bitonic sort, descending, fully unrolled (240 compare-exchanges)
#pragma unroll
        for (int k = 2; k <= 32; k <<= 1) {
#pragma unroll
            for (int j = k >> 1; j > 0; j >>= 1) {
#pragma unroll
                for (int i = 0; i < 32; ++i) {
                    const int l = i ^ j;
                    if (l > i) {
                        const float a = s[i], b = s[l];
                        const float hi = fmaxf(a, b), lo = fminf(a, b);
                        if ((i & k) == 0) { s[i] = hi; s[l] = lo; }
                        else              { s[i] = lo; s[l] = hi; }
                    }
                }
            }
        }
        float csum = 0.f, ssum = 0.f; int ksup = 0;
#pragma unroll
        for (int kk = 1; kk <= 32; ++kk) {
            const float zk = s[kk - 1];
            csum += zk;
            if (1.0f + (float)kk * zk > csum) { ksup += 1; ssum += zk; }
        }
        const float tau = (ssum - 1.0f) / (float)ksup;
#pragma unroll
        for (int j = 0; j < 32; ++j) zrow[j] = fmaxf(z[j] - tau, 0.f);
    }
    __syncthreads();

    // ---- weight -> gmem ----
    {
        float2* wg = (float2*)(weight + (size_t)blockIdx.x * 8192);
        const float* sc = (const float*)(smp + SCOR);
#pragma unroll
        for (int it = 0; it < 8; ++it) {
            const int idx = t + 512 * it;       // (gi, j)
            const int gi = idx >> 5, j = idx & 31;
            const int g = gi >> 5, i = gi & 31;
            float2 o;
            o.x = sc[(g * 64 + i) * SC_STRIDE + j];
            o.y = sc[(g * 64 + 32 + i) * SC_STRIDE + j];
            wg[idx] = o;
        }
    }

    // ---- phase V: V = X * WV (octets 0..31), staged into STG (T dead) ----
    proj_gemm(smp, sb, 0, (w >> 1) * 32, w & 1, lane, grp, q);
    __syncthreads();

    // ---- convert sparsemax weights (0.5-folded) to bf16 hi/lo into X region ----
    // layout: [256 rows p][32 cols j], rowbytes 64, chunk-XOR swizzle (conflict-free ldmatrix)
    {
        const float* sc = (const float*)(smp + SCOR);
        const int p = t >> 1, jh = (t & 1) * 16;
        const unsigned rsw = (((unsigned)p >> 1) & 3u) << 4;
        const unsigned rbase = (unsigned)(p * 64);
#pragma unroll
        for (int jj = 0; jj < 16; jj += 2) {
            const int j = jh + jj;
            const float2 f = *(const float2*)&sc[p * SC_STRIDE + j];
            unsigned hi, lo;
            split2(0.5f * f.x, 0.5f * f.y, hi, lo);
            const unsigned off = rbase + ((((unsigned)j >> 3) << 4) ^ rsw) + (unsigned)((j & 7) * 2);
            *(unsigned*)(smp + XHI + off) = hi;
            *(unsigned*)(smp + XLO + off) = lo;
        }
    }
    __syncthreads();

    // ---- phase O: warp (g, dq): O_g[32 x 32] = (0.5*w) * V, both heads in K ----
    {
        const int g = w >> 2, dq = w & 3;
        float D[4][2][4];
#pragma unroll
        for (int n = 0; n < 4; ++n)
#pragma unroll
            for (int m = 0; m < 2; ++m)
#pragma unroll
                for (int e = 0; e < 4; ++e) D[n][m][e] = 0.f;

        const unsigned offOB = (unsigned)((g * 32 + (mi & 1) * 8 + lr) * 512
                                          + (mi >> 1) * 16 + dq * 64);

#pragma unroll
        for (int kt = 0; kt < 4; ++kt) {
            const int h = kt >> 1, jb = (kt & 1) * 16;
            unsigned Ah[2][4], Al[2][4];
#pragma unroll
            for (int m = 0; m < 2; ++m) {
                const int prow = g * 64 + h * 32 + m * 16 + (mi & 1) * 8 + lr;
                const int cch = (jb >> 3) + (mi >> 1);
                const unsigned aoff = (unsigned)(prow * 64)
                    + (((unsigned)(cch ^ ((prow >> 1) & 3))) << 4);
                ldmx4(sb + XHI + aoff, Ah[m][0], Ah[m][1], Ah[m][2], Ah[m][3]);
                ldmx4(sb + XLO + aoff, Al[m][0], Al[m][1], Al[m][2], Al[m][3]);
            }
            const unsigned koff = (unsigned)((kt & 1) * 8192 + (kt >> 1) * 256);
            unsigned Bh[4][2], Bl[4][2];
            ldmx4t(sb + STGH + ((offOB + koff) ^ xsw),      Bh[0][0], Bh[0][1], Bh[1][0], Bh[1][1]);
            ldmx4t(sb + STGH + ((offOB + koff + 32) ^ xsw), Bh[2][0], Bh[2][1], Bh[3][0], Bh[3][1]);
            ldmx4t(sb + STGL + ((offOB + koff) ^ xsw),      Bl[0][0], Bl[0][1], Bl[1][0], Bl[1][1]);
            ldmx4t(sb + STGL + ((offOB + koff + 32) ^ xsw), Bl[2][0], Bl[2][1], Bl[3][0], Bl[3][1]);
            // pass-outer: per-accumulator order (AhBh, AlBh, AhBl) preserved
#pragma unroll
            for (int n = 0; n < 4; ++n)
#pragma unroll
                for (int m = 0; m < 2; ++m) mma_bf(D[n][m], Ah[m], Bh[n]);
#pragma unroll
            for (int n = 0; n < 4; ++n)
#pragma unroll
                for (int m = 0; m < 2; ++m) mma_bf(D[n][m], Al[m], Bh[n]);
#pragma unroll
            for (int n = 0; n < 4; ++n)
#pragma unroll
                for (int m = 0; m < 2; ++m) mma_bf(D[n][m], Ah[m], Bl[n]);
        }
        // out write
#pragma unroll
        for (int n = 0; n < 4; ++n)
#pragma unroll
            for (int m = 0; m < 2; ++m) {
                const int i = m * 16 + grp;
                const int d = dq * 32 + n * 8 + 2 * q;
                const size_t row = ((size_t)blockIdx.x * 4 + g) * 32 + i;
                float2 v0; v0.x = D[n][m][0]; v0.y = D[n][m][1];
                float2 v1; v1.x = D[n][m][2]; v1.y = D[n][m][3];
                *(float2*)&out[row * 128 + d] = v0;
                *(float2*)&out[(row + 8) * 128 + d] = v1;
            }
    }
}

extern "C" void kernel_launch(void* const* d_in, const int* in_sizes, int n_in,
                              void* d_out, int out_size)
{
    (void)in_sizes; (void)n_in; (void)out_size;
    const float* x  = (const float*)d_in[0];
    const float* WK = (const float*)d_in[1];
    const float* WV = (const float*)d_in[2];
    const float* WQ = (const float*)d_in[3];

    float* out    = (float*)d_out;
    float* weight = out + (size_t)4096 * 32 * 128;

    prep_w<<<512, 128>>>(WQ, WK, WV);

    cudaFuncSetAttribute(attn_hmma, cudaFuncAttributeMaxDynamicSharedMemorySize, SMEM_BYTES);
    attn_hmma<<<NBLK, THREADS, SMEM_BYTES>>>(x, out, weight);
}

// round 17
// speedup vs baseline: 1.8302x; 1.2079x over previous
#include <cuda_runtime.h>
#include <cuda_fp16.h>

#define THREADS 512
#define NBLK 1024

// ---- smem byte offsets ----
#define XHI 0u            // X hi  [128][128] fp16, rowbytes 256, swizzled   (32KB)
#define XLO 32768u        // w-fp16 hi [256][32], rowbytes 64, chunk-XOR swz (16KB used)
#define STGH 65536u       // stage hi [128][256] fp16, rowbytes 512, swz     (64KB)  T then V
#define STGL 131072u      // stage lo                                        (64KB)
#define SCOR 196608u      // scores/weights fp32 [256][34]                   (34816B)
#define SMEM_BYTES 231424u
#define SC_STRIDE 34

// packed W fragments: [octet o (0..63)][kt (0..7)][lane (0..31)] -> uint4 {bh0,bh1,bl0,bl1}
__device__ __align__(16) unsigned short g_wpk[64 * 8 * 32 * 8];

// ================= prep kernel =================
__global__ void prep_w(const float* __restrict__ WQ, const float* __restrict__ WK,
                       const float* __restrict__ WV)
{
    const int n = blockIdx.x, k1 = threadIdx.x;
    __shared__ float wk[128];
    float val;
    if (n < 256) {
        val = WV[k1 * 256 + n];
    } else {
        const int h = (n - 256) >> 7, k2 = (n - 256) & 127;
        wk[k1] = WK[k2 * 256 + h * 128 + k1];
        __syncthreads();
        const float* wq = WQ + k1 * 256 + h * 128;
        float acc = 0.f;
#pragma unroll 8
        for (int e = 0; e < 128; ++e) acc = fmaf(wq[e], wk[e], acc);
        val = acc * 0.0625f;       // fold 1/sqrt(D*H)
    }
    __half hi = __float2half_rn(val);
    __half lo = __float2half_rn(val - __half2float(hi));

    const int o = n >> 3, grp = n & 7;
    const int kt = k1 >> 4, rem = k1 & 15;
    const int half = rem >> 3, q = (rem & 7) >> 1, parity = rem & 1;
    const int lane = grp * 4 + q;
    const size_t base = ((size_t)((o * 8 + kt) * 32) + lane) * 8;
    g_wpk[base + half * 2 + parity]     = __half_as_ushort(hi);
    g_wpk[base + 4 + half * 2 + parity] = __half_as_ushort(lo);
}

// ================= helpers =================
__device__ __forceinline__ unsigned swz(int r, unsigned off) {
    return off ^ (((unsigned)r & 7u) << 4);
}
__device__ __forceinline__ void stsm(unsigned char* smp, unsigned base, int r, int c, int rb, unsigned v) {
    *(unsigned*)(smp + base + swz(r, (unsigned)(r * rb + c * 2))) = v;
}
__device__ __forceinline__ unsigned packh(float a, float b) {
    __half ha = __float2half_rn(a), hb = __float2half_rn(b);
    return ((unsigned)__half_as_ushort(hb) << 16) | (unsigned)__half_as_ushort(ha);
}
__device__ __forceinline__ void split2h(float a, float b, unsigned& hi, unsigned& lo) {
    __half ha = __float2half_rn(a), hb = __float2half_rn(b);
    float la = a - __half2float(ha), lb = b - __half2float(hb);
    __half lA = __float2half_rn(la), lB = __float2half_rn(lb);
    hi = ((unsigned)__half_as_ushort(hb) << 16) | (unsigned)__half_as_ushort(ha);
    lo = ((unsigned)__half_as_ushort(lB) << 16) | (unsigned)__half_as_ushort(lA);
}
__device__ __forceinline__ void mma_fp(float* d, const unsigned* a, const unsigned* b) {
    asm volatile(
        "mma.sync.aligned.m16n8k16.row.col.f32.f16.f16.f32 "
        "{%0,%1,%2,%3}, {%4,%5,%6,%7}, {%8,%9}, {%0,%1,%2,%3};\n"
        : "+f"(d[0]), "+f"(d[1]), "+f"(d[2]), "+f"(d[3])
        : "r"(a[0]), "r"(a[1]), "r"(a[2]), "r"(a[3]), "r"(b[0]), "r"(b[1]));
}
__device__ __forceinline__ void ldmx4(unsigned a, unsigned& r0, unsigned& r1,
                                      unsigned& r2, unsigned& r3) {
    asm volatile("ldmatrix.sync.aligned.m8n8.x4.shared.b16 {%0,%1,%2,%3}, [%4];"
                 : "=r"(r0), "=r"(r1), "=r"(r2), "=r"(r3) : "r"(a));
}
__device__ __forceinline__ void ldmx4t(unsigned a, unsigned& r0, unsigned& r1,
                                       unsigned& r2, unsigned& r3) {
    asm volatile("ldmatrix.sync.aligned.m8n8.x4.trans.shared.b16 {%0,%1,%2,%3}, [%4];"
                 : "=r"(r0), "=r"(r1), "=r"(r2), "=r"(r3) : "r"(a));
}

// projection GEMM: warp computes rows [mh*64, mh*64+64) x cols [nb, nb+32) of
// Y = X(128x128) * Wbig(128x512) slice.
// 2-pass fp16 compensated: D = Xh*Wh + Xh*Wl (X-lo dropped). A loaded once per kt.
__device__ __forceinline__ void proj_gemm(unsigned char* smp, unsigned sb,
                                          int nsel, int nb, int mh,
                                          int lane, int grp, int q)
{
    const int mi = lane >> 3, lr = lane & 7;
    const unsigned xsw = (unsigned)lr << 4;
    unsigned offA[4];
#pragma unroll
    for (int m = 0; m < 4; ++m)
        offA[m] = (unsigned)((mh * 64 + m * 16 + (mi & 1) * 8 + lr) * 256 + (mi >> 1) * 16);

    float D[4][4][4];   // [p = octet][m][4]
#pragma unroll
    for (int p = 0; p < 4; ++p)
#pragma unroll
        for (int m = 0; m < 4; ++m)
#pragma unroll
            for (int e = 0; e < 4; ++e) D[p][m][e] = 0.f;

    const uint4* wp = (const uint4*)g_wpk;
    const int ob = (nsel + nb) >> 3;
    unsigned wbase[4];
#pragma unroll
    for (int p = 0; p < 4; ++p)
        wbase[p] = (unsigned)((ob + p) * 256 + lane);

#pragma unroll
    for (int kt = 0; kt < 8; ++kt) {
        unsigned bh[4][2], bl[4][2];
#pragma unroll
        for (int p = 0; p < 4; ++p) {
            const uint4 v = wp[wbase[p] + kt * 32];
            bh[p][0] = v.x; bh[p][1] = v.y;
            bl[p][0] = v.z; bl[p][1] = v.w;
        }
        const unsigned ck = (unsigned)(kt * 32);
        unsigned A[4][4];
#pragma unroll
        for (int m = 0; m < 4; ++m)
            ldmx4(sb + XHI + ((offA[m] + ck) ^ xsw), A[m][0], A[m][1], A[m][2], A[m][3]);
#pragma unroll
        for (int p = 0; p < 4; ++p)
#pragma unroll
            for (int m = 0; m < 4; ++m) mma_fp(D[p][m], A[m], bh[p]);
#pragma unroll
        for (int p = 0; p < 4; ++p)
#pragma unroll
            for (int m = 0; m < 4; ++m) mma_fp(D[p][m], A[m], bl[p]);
    }

    // stage (split hi/lo fp16)
#pragma unroll
    for (int p = 0; p < 4; ++p)
#pragma unroll
        for (int m = 0; m < 4; ++m) {
            const int r0 = mh * 64 + m * 16 + grp;
            const int c = nb + p * 8 + 2 * q;
            unsigned hi, lo;
            split2h(D[p][m][0], D[p][m][1], hi, lo);
            stsm(smp, STGH, r0, c, 512, hi);
            stsm(smp, STGL, r0, c, 512, lo);
            split2h(D[p][m][2], D[p][m][3], hi, lo);
            stsm(smp, STGH, r0 + 8, c, 512, hi);
            stsm(smp, STGL, r0 + 8, c, 512, lo);
        }
}

// ================= main kernel: 1 CTA = 4 graphs, 16 warps =================
__global__ __launch_bounds__(THREADS, 1)
void attn_hmma(const float* __restrict__ x,
               float* __restrict__ out,      // [B*N, 128]
               float* __restrict__ weight)   // [B*N, 32, 2]
{
    extern __shared__ unsigned char smp[];
    const unsigned sb = (unsigned)__cvta_generic_to_shared(smp);
    const int t = threadIdx.x;
    const int w = t >> 5, lane = t & 31, grp = lane >> 2, q = lane & 3;
    const int mi = lane >> 3, lr = lane & 7;
    const unsigned xsw = (unsigned)lr << 4;

    // ---- load X, fp16 hi only ----
    {
        const float2* xg = (const float2*)(x + (size_t)blockIdx.x * 16384);
#pragma unroll
        for (int it = 0; it < 16; ++it) {
            const int e2 = t + 512 * it;
            const float2 v = xg[e2];
            const int r = e2 >> 6, c = (e2 & 63) * 2;
            stsm(smp, XHI, r, c, 256, packh(v.x, v.y));
        }
    }
    __syncthreads();

    // ---- phase T: T = X * A_h^T (octets 32..63), staged [128][256] (h,k2) ----
    proj_gemm(smp, sb, 256, (w >> 1) * 32, w & 1, lane, grp, q);
    __syncthreads();

    // ---- phase S: warp (g, h, ih): 16 i-rows of S_gh[32x32] = T_gh * X_g^T ----
    // 2-pass: Th*Xh + Tl*Xh (X-lo dropped)
    {
        const int g = w >> 2, h = (w >> 1) & 1, ih = w & 1;
        float D[4][4];
#pragma unroll
        for (int nt = 0; nt < 4; ++nt)
#pragma unroll
            for (int e = 0; e < 4; ++e) D[nt][e] = 0.f;

        const unsigned offSA = (unsigned)((g * 32 + ih * 16 + (mi & 1) * 8 + lr) * 512
                                          + (mi >> 1) * 16 + h * 256);
        const unsigned offSB = (unsigned)((g * 32 + (mi >> 1) * 8 + lr) * 256 + (mi & 1) * 16);

#pragma unroll
        for (int kt = 0; kt < 8; ++kt) {
            const unsigned ck = (unsigned)(kt * 32);
            unsigned Ah[4], Al[4];
            ldmx4(sb + STGH + ((offSA + ck) ^ xsw), Ah[0], Ah[1], Ah[2], Ah[3]);
            ldmx4(sb + STGL + ((offSA + ck) ^ xsw), Al[0], Al[1], Al[2], Al[3]);
            unsigned Bh[4][2];
            ldmx4(sb + XHI + ((offSB + ck) ^ xsw),        Bh[0][0], Bh[0][1], Bh[1][0], Bh[1][1]);
            ldmx4(sb + XHI + ((offSB + 4096 + ck) ^ xsw), Bh[2][0], Bh[2][1], Bh[3][0], Bh[3][1]);
            // pass-outer: per-accumulator order (AhBh, AlBh) preserved
#pragma unroll
            for (int nt = 0; nt < 4; ++nt) mma_fp(D[nt], Ah, Bh[nt]);
#pragma unroll
            for (int nt = 0; nt < 4; ++nt) mma_fp(D[nt], Al, Bh[nt]);
        }
        // stage scores fp32
        float* sc = (float*)(smp + SCOR);
#pragma unroll
        for (int nt = 0; nt < 4; ++nt) {
            const int p = g * 64 + h * 32 + ih * 16 + grp;
            const int j = nt * 8 + 2 * q;
            float2 v0; v0.x = D[nt][0]; v0.y = D[nt][1];
            float2 v1; v1.x = D[nt][2]; v1.y = D[nt][3];
            *(float2*)&sc[p * SC_STRIDE + j] = v0;
            *(float2*)&sc[(p + 8) * SC_STRIDE + j] = v1;
        }
    }
    __syncthreads();

    // ---- sparsemax: thread t<256 owns problem p = t; writes fp32 + fp16(0.5w) ----
    if (t < 256) {
        float* zrow = (float*)(smp + SCOR) + t * SC_STRIDE;
        float z[32], s[32];
#pragma unroll
        for (int j = 0; j < 32; ++j) { z[j] = zrow[j]; s[j] = z[j]; }
        // bitonic sort, descending, fully unrolled (240 compare-exchanges)
#pragma unroll
        for (int k = 2; k <= 32; k <<= 1) {
#pragma unroll
            for (int j = k >> 1; j > 0; j >>= 1) {
#pragma unroll
                for (int i = 0; i < 32; ++i) {
                    const int l = i ^ j;
                    if (l > i) {
                        const float a = s[i], b = s[l];
                        const float hi = fmaxf(a, b), lo = fminf(a, b);
                        if ((i & k) == 0) { s[i] = hi; s[l] = lo; }
                        else              { s[i] = lo; s[l] = hi; }
                    }
                }
            }
        }
        float csum = 0.f, ssum = 0.f; int ksup = 0;
#pragma unroll
        for (int kk = 1; kk <= 32; ++kk) {
            const float zk = s[kk - 1];
            csum += zk;
            if (1.0f + (float)kk * zk > csum) { ksup += 1; ssum += zk; }
        }
        const float tau = (ssum - 1.0f) / (float)ksup;

        const unsigned rsw = (((unsigned)t >> 1) & 3u) << 4;
        const unsigned rbase = (unsigned)(t * 64);
#pragma unroll
        for (int j = 0; j < 32; j += 2) {
            const float w0 = fmaxf(z[j] - tau, 0.f);
            const float w1 = fmaxf(z[j + 1] - tau, 0.f);
            zrow[j] = w0; zrow[j + 1] = w1;
            const unsigned off = rbase + ((((unsigned)j >> 3) << 4) ^ rsw) + (unsigned)((j & 7) * 2);
            *(unsigned*)(smp + XLO + off) = packh(0.5f * w0, 0.5f * w1);
        }
    }
    __syncthreads();

    // ---- weight -> gmem ----
    {
        float2* wg = (float2*)(weight + (size_t)blockIdx.x * 8192);
        const float* sc = (const float*)(smp + SCOR);
#pragma unroll
        for (int it = 0; it < 8; ++it) {
            const int idx = t + 512 * it;       // (gi, j)
            const int gi = idx >> 5, j = idx & 31;
            const int g = gi >> 5, i = gi & 31;
            float2 o;
            o.x = sc[(g * 64 + i) * SC_STRIDE + j];
            o.y = sc[(g * 64 + 32 + i) * SC_STRIDE + j];
            wg[idx] = o;
        }
    }

    // ---- phase V: V = X * WV (octets 0..31), staged into STG (T dead) ----
    proj_gemm(smp, sb, 0, (w >> 1) * 32, w & 1, lane, grp, q);
    __syncthreads();

    // ---- phase O: warp (g, dq): O_g[32 x 32] = (0.5*w) * V, both heads in K ----
    // 2-pass: Wh*Vh + Wh*Vl (w-lo dropped)
    {
        const int g = w >> 2, dq = w & 3;
        float D[4][2][4];
#pragma unroll
        for (int n = 0; n < 4; ++n)
#pragma unroll
            for (int m = 0; m < 2; ++m)
#pragma unroll
                for (int e = 0; e < 4; ++e) D[n][m][e] = 0.f;

        const unsigned offOB = (unsigned)((g * 32 + (mi & 1) * 8 + lr) * 512
                                          + (mi >> 1) * 16 + dq * 64);

#pragma unroll
        for (int kt = 0; kt < 4; ++kt) {
            const int h = kt >> 1, jb = (kt & 1) * 16;
            unsigned Ah[2][4];
#pragma unroll
            for (int m = 0; m < 2; ++m) {
                const int prow = g * 64 + h * 32 + m * 16 + (mi & 1) * 8 + lr;
                const int cch = (jb >> 3) + (mi >> 1);
                const unsigned aoff = (unsigned)(prow * 64)
                    + (((unsigned)(cch ^ ((prow >> 1) & 3))) << 4);
                ldmx4(sb + XLO + aoff, Ah[m][0], Ah[m][1], Ah[m][2], Ah[m][3]);
            }
            const unsigned koff = (unsigned)((kt & 1) * 8192 + (kt >> 1) * 256);
            unsigned Bh[4][2], Bl[4][2];
            ldmx4t(sb + STGH + ((offOB + koff) ^ xsw),      Bh[0][0], Bh[0][1], Bh[1][0], Bh[1][1]);
            ldmx4t(sb + STGH + ((offOB + koff + 32) ^ xsw), Bh[2][0], Bh[2][1], Bh[3][0], Bh[3][1]);
            ldmx4t(sb + STGL + ((offOB + koff) ^ xsw),      Bl[0][0], Bl[0][1], Bl[1][0], Bl[1][1]);
            ldmx4t(sb + STGL + ((offOB + koff + 32) ^ xsw), Bl[2][0], Bl[2][1], Bl[3][0], Bl[3][1]);
            // pass-outer: per-accumulator order (AhBh, AhBl) preserved
#pragma unroll
            for (int n = 0; n < 4; ++n)
#pragma unroll
                for (int m = 0; m < 2; ++m) mma_fp(D[n][m], Ah[m], Bh[n]);
#pragma unroll
            for (int n = 0; n < 4; ++n)
#pragma unroll
                for (int m = 0; m < 2; ++m) mma_fp(D[n][m], Ah[m], Bl[n]);
        }
        // out write
#pragma unroll
        for (int n = 0; n < 4; ++n)
#pragma unroll
            for (int m = 0; m < 2; ++m) {
                const int i = m * 16 + grp;
                const int d = dq * 32 + n * 8 + 2 * q;
                const size_t row = ((size_t)blockIdx.x * 4 + g) * 32 + i;
                float2 v0; v0.x = D[n][m][0]; v0.y = D[n][m][1];
                float2 v1; v1.x = D[n][m][2]; v1.y = D[n][m][3];
                *(float2*)&out[row * 128 + d] = v0;
                *(float2*)&out[(row + 8) * 128 + d] = v1;
            }
    }
}

extern "C" void kernel_launch(void* const* d_in, const int* in_sizes, int n_in,
                              void* d_out, int out_size)
{
    (void)in_sizes; (void)n_in; (void)out_size;
    const float* x  = (const float*)d_in[0];
    const float* WK = (const float*)d_in[1];
    const float* WV = (const float*)d_in[2];
    const float* WQ = (const float*)d_in[3];

    float* out    = (float*)d_out;
    float* weight = out + (size_t)4096 * 32 * 128;

    prep_w<<<512, 128>>>(WQ, WK, WV);

    cudaFuncSetAttribute(attn_hmma, cudaFuncAttributeMaxDynamicSharedMemorySize, SMEM_BYTES);
    attn_hmma<<<NBLK, THREADS, SMEM_BYTES>>>(x, out, weight);
}